// round 5
// baseline (speedup 1.0000x reference)
#include <cuda_runtime.h>

#define NN 50000
#define NE 800000

// ---------------- scratch ----------------
__device__ __align__(16) float g_PQ  [NN * 512];   // [N,512]: P | Q
__device__ __align__(16) float g_m   [NE * 256];   // edge hidden (tf32 bits), slot order
__device__ __align__(16) float g_ef  [NE * 256];   // edge features (tf32 bits), slot order
__device__ __align__(16) float g_agg [NN * 256];
__device__ __align__(16) float g_hmid[NN * 256];
__device__ __align__(16) float g_phi [NE];         // slot order
__device__ __align__(16) float g_W1ab[512 * 256];
__device__ __align__(16) float g_We2t[256 * 256];  // tf32 bits
__device__ __align__(16) float g_Wc1t[256 * 256];  // tf32 bits
__device__ __align__(16) float g_wr  [256];
__device__ __align__(16) float g_b512[512];
// CSR
__device__ int g_hist[NN];
__device__ int g_tmp [NN];
__device__ int g_rptr[NN + 1];
__device__ int g_prow[NE];
__device__ int g_pcol[NE];

// ---------------- helpers ----------------
__device__ __forceinline__ float siluf(float x) {
    return x * (1.0f / (1.0f + __expf(-x)));
}
__device__ __forceinline__ unsigned f2tf(float x) {
    unsigned r; asm("cvt.rna.tf32.f32 %0, %1;" : "=r"(r) : "f"(x)); return r;
}
__device__ __forceinline__ void mma8(float d[4], const unsigned a[4], const unsigned b[2]) {
    asm volatile(
        "mma.sync.aligned.m16n8k8.row.col.f32.tf32.tf32.f32 "
        "{%0,%1,%2,%3}, {%4,%5,%6,%7}, {%8,%9}, {%0,%1,%2,%3};\n"
        : "+f"(d[0]), "+f"(d[1]), "+f"(d[2]), "+f"(d[3])
        : "r"(a[0]), "r"(a[1]), "r"(a[2]), "r"(a[3]), "r"(b[0]), "r"(b[1]));
}
__device__ __forceinline__ void cpa16(unsigned saddr, const float* g) {
    asm volatile("cp.async.cg.shared.global [%0], [%1], 16;" :: "r"(saddr), "l"(g));
}

// ---------------- CSR construction ----------------
__global__ void zero_int_kernel() {
    int i = blockIdx.x * blockDim.x + threadIdx.x;
    if (i < NN) { g_hist[i] = 0; g_tmp[i] = 0; }
}
__global__ void hist_kernel(const int* __restrict__ ei) {
    int e = blockIdx.x * blockDim.x + threadIdx.x;
    if (e < NE) atomicAdd(&g_hist[ei[e]], 1);
}
__global__ void scan_kernel() {  // 1 block, 1024 threads
    __shared__ int part[1024];
    const int t = threadIdx.x;
    const int CH = (NN + 1023) / 1024;  // 49
    int base = t * CH;
    int end = base + CH; if (end > NN) end = NN;
    int s = 0;
    for (int i = base; i < end; i++) s += g_hist[i];
    part[t] = s;
    __syncthreads();
    for (int off = 1; off < 1024; off <<= 1) {
        int v = (t >= off) ? part[t - off] : 0;
        __syncthreads();
        part[t] += v;
        __syncthreads();
    }
    int run = (t == 0) ? 0 : part[t - 1];
    for (int i = base; i < end; i++) { g_rptr[i] = run; run += g_hist[i]; }
    if (t == 1023) g_rptr[NN] = NE;
}
__global__ void scatter_kernel(const int* __restrict__ ei) {
    int e = blockIdx.x * blockDim.x + threadIdx.x;
    if (e >= NE) return;
    int r = ei[e], c = ei[NE + e];
    int pos = atomicAdd(&g_tmp[r], 1);
    int s = g_rptr[r] + pos;
    g_prow[s] = r;
    g_pcol[s] = c;
}

// ---------------- weight packing ----------------
__global__ void pack_weights(const float* __restrict__ We1, const float* __restrict__ be1,
                             const float* __restrict__ We2, const float* __restrict__ Wc1) {
    int i = blockIdx.x * blockDim.x + threadIdx.x;
    if (i < 512 * 256) {
        int n = i >> 8, k = i & 255;
        g_W1ab[i] = (n < 256) ? We1[n * 513 + k] : We1[(n - 256) * 513 + 256 + k];
    }
    if (i < 256 * 256) {
        g_We2t[i] = __uint_as_float(f2tf(We2[i]));
        g_Wc1t[i] = __uint_as_float(f2tf(Wc1[i]));
    }
    if (i < 256) g_wr[i] = We1[i * 513 + 512];
    if (i < 512) g_b512[i] = (i < 256) ? be1[i] : 0.0f;
}

// ---------------- per-slot m = tf32(SiLU(P[row] + Q[col] + rad*wr)) ----------------
__global__ void edge_m_kernel(const float* __restrict__ coord) {
    int s = blockIdx.x * 8 + (threadIdx.x >> 5);
    if (s >= NE) return;
    int lane = threadIdx.x & 31;
    int r = g_prow[s];
    int c = g_pcol[s];
    float dx = coord[3 * r + 0] - coord[3 * c + 0];
    float dy = coord[3 * r + 1] - coord[3 * c + 1];
    float dz = coord[3 * r + 2] - coord[3 * c + 2];
    float rad = dx * dx + dy * dy + dz * dz;
    const float4* PQ4 = (const float4*)g_PQ;
    const float4* wr4 = (const float4*)g_wr;
    float4* m4 = (float4*)g_m;
#pragma unroll
    for (int it = 0; it < 2; it++) {
        int q = lane + it * 32;
        float4 p  = PQ4[(size_t)r * 128 + q];
        float4 qq = PQ4[(size_t)c * 128 + 64 + q];
        float4 w  = wr4[q];
        float4 v;
        v.x = __uint_as_float(f2tf(siluf(p.x + qq.x + rad * w.x)));
        v.y = __uint_as_float(f2tf(siluf(p.y + qq.y + rad * w.y)));
        v.z = __uint_as_float(f2tf(siluf(p.z + qq.z + rad * w.z)));
        v.w = __uint_as_float(f2tf(siluf(p.w + qq.w + rad * w.w)));
        m4[(size_t)s * 64 + q] = v;
    }
}

// ---------------- agg gather: per node, contiguous ef slots ----------------
__global__ void agg_gather_kernel() {
    int n = blockIdx.x * 8 + (threadIdx.x >> 5);
    if (n >= NN) return;
    int lane = threadIdx.x & 31;
    int s0 = g_rptr[n], s1 = g_rptr[n + 1];
    const float4* ef4 = (const float4*)g_ef;
    float4 a0 = make_float4(0, 0, 0, 0);
    float4 a1 = make_float4(0, 0, 0, 0);
    for (int s = s0; s < s1; s++) {
        float4 v0 = ef4[(size_t)s * 64 + lane * 2];
        float4 v1 = ef4[(size_t)s * 64 + lane * 2 + 1];
        a0.x += v0.x; a0.y += v0.y; a0.z += v0.z; a0.w += v0.w;
        a1.x += v1.x; a1.y += v1.y; a1.z += v1.z; a1.w += v1.w;
    }
    float4* agg4 = (float4*)g_agg;
    agg4[(size_t)n * 64 + lane * 2]     = a0;
    agg4[(size_t)n * 64 + lane * 2 + 1] = a1;
}

// ---------------- coord out: per node gather of phi * coord_diff ----------------
__global__ void coord_out_kernel(const float* __restrict__ coord, float* __restrict__ outc) {
    int n = blockIdx.x * 8 + (threadIdx.x >> 5);
    if (n >= NN) return;
    int lane = threadIdx.x & 31;
    int s0 = g_rptr[n], s1 = g_rptr[n + 1];
    float cx = coord[3 * n + 0], cy = coord[3 * n + 1], cz = coord[3 * n + 2];
    float sx = 0.0f, sy = 0.0f, sz = 0.0f;
    for (int s = s0 + lane; s < s1; s += 32) {
        int c = g_pcol[s];
        float p = g_phi[s];
        sx += (cx - coord[3 * c + 0]) * p;
        sy += (cy - coord[3 * c + 1]) * p;
        sz += (cz - coord[3 * c + 2]) * p;
    }
#pragma unroll
    for (int off = 16; off > 0; off >>= 1) {
        sx += __shfl_xor_sync(0xffffffffu, sx, off);
        sy += __shfl_xor_sync(0xffffffffu, sy, off);
        sz += __shfl_xor_sync(0xffffffffu, sz, off);
    }
    if (lane == 0) {
        float d = (float)(s1 - s0);
        if (d < 1.0f) d = 1.0f;
        outc[3 * n + 0] = cx + sx / d;
        outc[3 * n + 1] = cy + sy / d;
        outc[3 * n + 2] = cz + sz / d;
    }
}

// =====================================================================
// Async edge GEMM, 4-stage cp.async: C = epilogue(A[NE,256] @ W[256,256]^T)
//   MODE EF : ef = tf32(SiLU(acc+be2))  (plain store, no atomics)
//   MODE PHI: phi[row] = sum_col SiLU(acc+bc1)*wc2[col]  (smem reduce, plain store)
// =====================================================================
#define PST 36            // padded stride (words)
#define STG_A (128 * PST)
#define STG_B (256 * PST)
#define STG_W (STG_A + STG_B)   // 13824 words
#define NSTG 4
#define ESMEM_WORDS (NSTG * STG_W)

enum { EMODE_EF = 0, EMODE_PHI = 1 };

template <int MODE>
__global__ void __launch_bounds__(256, 1)
egemm(const float* __restrict__ A, const float* __restrict__ W,
      const float* __restrict__ bias, float* __restrict__ C,
      const float* __restrict__ wc2, float* __restrict__ phi)
{
    extern __shared__ float esm[];
    const int tid  = threadIdx.x;
    const int lane = tid & 31;
    const int warp = tid >> 5;
    const int wm = (warp & 1) * 64;
    const int wn = (warp >> 1) * 64;
    const int blockM = blockIdx.x * 128;
    const unsigned sbase = (unsigned)__cvta_generic_to_shared(esm);

    float acc[4][8][4];
#pragma unroll
    for (int i = 0; i < 4; i++)
#pragma unroll
        for (int j = 0; j < 8; j++)
#pragma unroll
            for (int q = 0; q < 4; q++) acc[i][j][q] = 0.0f;

#define ISSUE_TILE(stage, k0)                                                        \
    do {                                                                             \
        _Pragma("unroll")                                                            \
        for (int i = 0; i < 4; i++) {                                                \
            int ch = tid + i * 256;                                                  \
            int r = ch >> 3, c = (ch & 7) * 4;                                       \
            cpa16(sbase + ((stage) * STG_W + r * PST + c) * 4,                       \
                  A + (size_t)(blockM + r) * 256 + (k0) + c);                        \
        }                                                                            \
        _Pragma("unroll")                                                            \
        for (int i = 0; i < 8; i++) {                                                \
            int ch = tid + i * 256;                                                  \
            int r = ch >> 3, c = (ch & 7) * 4;                                       \
            cpa16(sbase + ((stage) * STG_W + STG_A + r * PST + c) * 4,               \
                  W + (size_t)r * 256 + (k0) + c);                                   \
        }                                                                            \
        asm volatile("cp.async.commit_group;");                                      \
    } while (0)

    ISSUE_TILE(0, 0);
    ISSUE_TILE(1, 32);
    ISSUE_TILE(2, 64);

#pragma unroll 1
    for (int kt = 0; kt < 8; kt++) {
        __syncthreads();  // readers of the stage being overwritten are done
        if (kt + 3 < 8) {
            ISSUE_TILE((kt + 3) % NSTG, (kt + 3) * 32);
            asm volatile("cp.async.wait_group 3;");
        } else if (kt + 2 < 8) {
            asm volatile("cp.async.wait_group 2;");
        } else if (kt + 1 < 8) {
            asm volatile("cp.async.wait_group 1;");
        } else {
            asm volatile("cp.async.wait_group 0;");
        }
        __syncthreads();  // publish completed stage

        const unsigned* as = (const unsigned*)(esm + (kt % NSTG) * STG_W);
        const unsigned* bs = as + STG_A;
#pragma unroll
        for (int kk = 0; kk < 32; kk += 8) {
            unsigned af[4][4];
#pragma unroll
            for (int mt = 0; mt < 4; mt++) {
                int r = wm + mt * 16 + (lane >> 2);
                int c = kk + (lane & 3);
                af[mt][0] = as[r * PST + c];
                af[mt][1] = as[(r + 8) * PST + c];
                af[mt][2] = as[r * PST + c + 4];
                af[mt][3] = as[(r + 8) * PST + c + 4];
            }
            unsigned bf[8][2];
#pragma unroll
            for (int nt = 0; nt < 8; nt++) {
                int n = wn + nt * 8 + (lane >> 2);
                int c = kk + (lane & 3);
                bf[nt][0] = bs[n * PST + c];
                bf[nt][1] = bs[n * PST + c + 4];
            }
#pragma unroll
            for (int mt = 0; mt < 4; mt++)
#pragma unroll
                for (int nt = 0; nt < 8; nt++)
                    mma8(acc[mt][nt], af[mt], bf[nt]);
        }
    }
#undef ISSUE_TILE

    // ---- epilogue ----
    float* sphi = esm;  // reuse smem in PHI mode
    if (MODE == EMODE_PHI) {
        __syncthreads();
        if (tid < 128) sphi[tid] = 0.0f;
        __syncthreads();
    }
#pragma unroll
    for (int mt = 0; mt < 4; mt++) {
        int loc0 = wm + mt * 16 + (lane >> 2);   // local row 0..127
        float pp[2]; pp[0] = 0.0f; pp[1] = 0.0f;
#pragma unroll
        for (int h2 = 0; h2 < 2; h2++) {
            int row = blockM + loc0 + h2 * 8;
#pragma unroll
            for (int nt = 0; nt < 8; nt++) {
                int col = wn + nt * 8 + (lane & 3) * 2;
                float v0 = acc[mt][nt][h2 * 2 + 0];
                float v1 = acc[mt][nt][h2 * 2 + 1];
                if (MODE == EMODE_EF) {
                    v0 = siluf(v0 + bias[col]);
                    v1 = siluf(v1 + bias[col + 1]);
                    float2 st;
                    st.x = __uint_as_float(f2tf(v0));
                    st.y = __uint_as_float(f2tf(v1));
                    *(float2*)&C[(size_t)row * 256 + col] = st;
                } else {
                    v0 = siluf(v0 + bias[col]);
                    v1 = siluf(v1 + bias[col + 1]);
                    pp[h2] += v0 * wc2[col] + v1 * wc2[col + 1];
                }
            }
        }
        if (MODE == EMODE_PHI) {
            pp[0] += __shfl_xor_sync(0xffffffffu, pp[0], 1);
            pp[0] += __shfl_xor_sync(0xffffffffu, pp[0], 2);
            pp[1] += __shfl_xor_sync(0xffffffffu, pp[1], 1);
            pp[1] += __shfl_xor_sync(0xffffffffu, pp[1], 2);
            if ((lane & 3) == 0) {
                atomicAdd(&sphi[loc0], pp[0]);
                atomicAdd(&sphi[loc0 + 8], pp[1]);
            }
        }
    }
    if (MODE == EMODE_PHI) {
        __syncthreads();
        if (tid < 128) phi[blockM + tid] = sphi[tid];
    }
}

// ---------------- node GEMM (proven path) ----------------
#define BM 128
#define BN 256
#define BK 32
#define SST 36

enum { MODE_PLAIN = 0, MODE_CAT = 3, MODE_NODE2 = 4 };

template <int MODE>
__global__ void __launch_bounds__(256, 1)
gemm_kernel(const float* __restrict__ A, const float* __restrict__ A2,
            const float* __restrict__ W, const float* __restrict__ bias,
            float* __restrict__ C, int ldc, int M, int K,
            const float* __restrict__ resid)
{
    extern __shared__ unsigned smem[];
    unsigned* Abase = smem;
    unsigned* Bbase = smem + 2 * BM * SST;

    const int tid  = threadIdx.x;
    const int lane = tid & 31;
    const int warp = tid >> 5;
    const int wm = (warp & 1) * 64;
    const int wn = (warp >> 1) * 64;
    const int blockM = blockIdx.x * BM;
    const int blockN = blockIdx.y * BN;
    const int ldr = tid >> 3;
    const int lkq = (tid & 7) * 4;

    float acc[4][8][4];
#pragma unroll
    for (int i = 0; i < 4; i++)
#pragma unroll
        for (int j = 0; j < 8; j++)
#pragma unroll
            for (int q = 0; q < 4; q++) acc[i][j][q] = 0.0f;

    float4 ra[4];
    float4 rb[8];
    const int ktiles = K / BK;

    {
        const int k0 = 0;
#pragma unroll
        for (int i = 0; i < 4; i++) {
            int r = blockM + ldr + i * 32;
            const float* s;
            if (MODE == MODE_CAT)
                s = (k0 + lkq < 256) ? (A + (size_t)r * 256 + k0 + lkq)
                                     : (A2 + (size_t)r * 256 + (k0 + lkq - 256));
            else
                s = A + (size_t)r * K + k0 + lkq;
            ra[i] = (r < M) ? *(const float4*)s : make_float4(0, 0, 0, 0);
        }
#pragma unroll
        for (int i = 0; i < 8; i++) {
            int n = blockN + ldr + i * 32;
            rb[i] = *(const float4*)(W + (size_t)n * K + k0 + lkq);
        }
        unsigned* as = Abase;
        unsigned* bs = Bbase;
#pragma unroll
        for (int i = 0; i < 4; i++) {
            uint4 t; t.x = f2tf(ra[i].x); t.y = f2tf(ra[i].y); t.z = f2tf(ra[i].z); t.w = f2tf(ra[i].w);
            *(uint4*)(as + (ldr + i * 32) * SST + lkq) = t;
        }
#pragma unroll
        for (int i = 0; i < 8; i++) {
            uint4 t; t.x = f2tf(rb[i].x); t.y = f2tf(rb[i].y); t.z = f2tf(rb[i].z); t.w = f2tf(rb[i].w);
            *(uint4*)(bs + (ldr + i * 32) * SST + lkq) = t;
        }
    }
    __syncthreads();

    for (int t = 0; t < ktiles; ++t) {
        if (t + 1 < ktiles) {
            const int k0 = (t + 1) * BK;
#pragma unroll
            for (int i = 0; i < 4; i++) {
                int r = blockM + ldr + i * 32;
                const float* s;
                if (MODE == MODE_CAT)
                    s = (k0 + lkq < 256) ? (A + (size_t)r * 256 + k0 + lkq)
                                         : (A2 + (size_t)r * 256 + (k0 + lkq - 256));
                else
                    s = A + (size_t)r * K + k0 + lkq;
                ra[i] = (r < M) ? *(const float4*)s : make_float4(0, 0, 0, 0);
            }
#pragma unroll
            for (int i = 0; i < 8; i++) {
                int n = blockN + ldr + i * 32;
                rb[i] = *(const float4*)(W + (size_t)n * K + k0 + lkq);
            }
        }
        const unsigned* as = Abase + (t & 1) * BM * SST;
        const unsigned* bs = Bbase + (t & 1) * BN * SST;
#pragma unroll
        for (int kk = 0; kk < BK; kk += 8) {
            unsigned af[4][4];
#pragma unroll
            for (int mt = 0; mt < 4; mt++) {
                int r = wm + mt * 16 + (lane >> 2);
                int c = kk + (lane & 3);
                af[mt][0] = as[r * SST + c];
                af[mt][1] = as[(r + 8) * SST + c];
                af[mt][2] = as[r * SST + c + 4];
                af[mt][3] = as[(r + 8) * SST + c + 4];
            }
            unsigned bf[8][2];
#pragma unroll
            for (int nt = 0; nt < 8; nt++) {
                int n = wn + nt * 8 + (lane >> 2);
                int c = kk + (lane & 3);
                bf[nt][0] = bs[n * SST + c];
                bf[nt][1] = bs[n * SST + c + 4];
            }
#pragma unroll
            for (int mt = 0; mt < 4; mt++)
#pragma unroll
                for (int nt = 0; nt < 8; nt++)
                    mma8(acc[mt][nt], af[mt], bf[nt]);
        }
        if (t + 1 < ktiles) {
            unsigned* asw = Abase + ((t + 1) & 1) * BM * SST;
            unsigned* bsw = Bbase + ((t + 1) & 1) * BN * SST;
#pragma unroll
            for (int i = 0; i < 4; i++) {
                uint4 tt; tt.x = f2tf(ra[i].x); tt.y = f2tf(ra[i].y); tt.z = f2tf(ra[i].z); tt.w = f2tf(ra[i].w);
                *(uint4*)(asw + (ldr + i * 32) * SST + lkq) = tt;
            }
#pragma unroll
            for (int i = 0; i < 8; i++) {
                uint4 tt; tt.x = f2tf(rb[i].x); tt.y = f2tf(rb[i].y); tt.z = f2tf(rb[i].z); tt.w = f2tf(rb[i].w);
                *(uint4*)(bsw + (ldr + i * 32) * SST + lkq) = tt;
            }
            __syncthreads();
        }
    }

#pragma unroll
    for (int mt = 0; mt < 4; mt++) {
#pragma unroll
        for (int h2 = 0; h2 < 2; h2++) {
            int row = blockM + wm + mt * 16 + (lane >> 2) + h2 * 8;
            if (row < M) {
#pragma unroll
                for (int nt = 0; nt < 8; nt++) {
                    int col = blockN + wn + nt * 8 + (lane & 3) * 2;
                    float v0 = acc[mt][nt][h2 * 2 + 0];
                    float v1 = acc[mt][nt][h2 * 2 + 1];
                    if (MODE == MODE_PLAIN) {
                        v0 += bias[col]; v1 += bias[col + 1];
                        *(float2*)&C[(size_t)row * ldc + col] = make_float2(v0, v1);
                    } else if (MODE == MODE_CAT) {
                        v0 = siluf(v0 + bias[col]);
                        v1 = siluf(v1 + bias[col + 1]);
                        *(float2*)&C[(size_t)row * ldc + col] = make_float2(v0, v1);
                    } else {  // MODE_NODE2
                        v0 += bias[col] + resid[(size_t)row * ldc + col];
                        v1 += bias[col + 1] + resid[(size_t)row * ldc + col + 1];
                        *(float2*)&C[(size_t)row * ldc + col] = make_float2(v0, v1);
                    }
                }
            }
        }
    }
}

// ---------------- host ----------------
extern "C" void kernel_launch(void* const* d_in, const int* in_sizes, int n_in,
                              void* d_out, int out_size)
{
    (void)in_sizes; (void)n_in; (void)out_size;
    const float* h     = (const float*)d_in[0];
    const int*   ei    = (const int*)  d_in[1];
    const float* coord = (const float*)d_in[2];
    const float* We1   = (const float*)d_in[3];
    const float* be1   = (const float*)d_in[4];
    const float* We2   = (const float*)d_in[5];
    const float* be2   = (const float*)d_in[6];
    const float* Wn1   = (const float*)d_in[7];
    const float* bn1   = (const float*)d_in[8];
    const float* Wn2   = (const float*)d_in[9];
    const float* bn2   = (const float*)d_in[10];
    const float* Wc1   = (const float*)d_in[11];
    const float* bc1   = (const float*)d_in[12];
    const float* Wc2   = (const float*)d_in[13];
    float* outh = (float*)d_out;
    float* outc = outh + (size_t)NN * 256;

    float *pPQ, *pm, *pef, *pagg, *phmid, *pphi, *pW1ab, *pb512, *pWe2t, *pWc1t;
    cudaGetSymbolAddress((void**)&pPQ,   g_PQ);
    cudaGetSymbolAddress((void**)&pm,    g_m);
    cudaGetSymbolAddress((void**)&pef,   g_ef);
    cudaGetSymbolAddress((void**)&pagg,  g_agg);
    cudaGetSymbolAddress((void**)&phmid, g_hmid);
    cudaGetSymbolAddress((void**)&pphi,  g_phi);
    cudaGetSymbolAddress((void**)&pW1ab, g_W1ab);
    cudaGetSymbolAddress((void**)&pb512, g_b512);
    cudaGetSymbolAddress((void**)&pWe2t, g_We2t);
    cudaGetSymbolAddress((void**)&pWc1t, g_Wc1t);

    const int SMEMB  = (2 * BM * SST + 2 * BN * SST) * 4;  // 110592
    const int ESMEMB = ESMEM_WORDS * 4;                    // 221184
    cudaFuncSetAttribute((const void*)gemm_kernel<MODE_PLAIN>, cudaFuncAttributeMaxDynamicSharedMemorySize, SMEMB);
    cudaFuncSetAttribute((const void*)gemm_kernel<MODE_CAT>,   cudaFuncAttributeMaxDynamicSharedMemorySize, SMEMB);
    cudaFuncSetAttribute((const void*)gemm_kernel<MODE_NODE2>, cudaFuncAttributeMaxDynamicSharedMemorySize, SMEMB);
    cudaFuncSetAttribute((const void*)egemm<EMODE_EF>,  cudaFuncAttributeMaxDynamicSharedMemorySize, ESMEMB);
    cudaFuncSetAttribute((const void*)egemm<EMODE_PHI>, cudaFuncAttributeMaxDynamicSharedMemorySize, ESMEMB);

    // CSR build
    zero_int_kernel<<<(NN + 255) / 256, 256>>>();
    hist_kernel<<<(NE + 255) / 256, 256>>>(ei);
    scan_kernel<<<1, 1024>>>();
    scatter_kernel<<<(NE + 255) / 256, 256>>>(ei);

    pack_weights<<<512, 256>>>(We1, be1, We2, Wc1);

    // PQ = h @ [We1a;We1b]^T + [be1;0]
    gemm_kernel<MODE_PLAIN><<<dim3((NN + BM - 1) / BM, 2), 256, SMEMB>>>(
        h, nullptr, pW1ab, pb512, pPQ, 512, NN, 256, nullptr);

    // m (slot order)
    edge_m_kernel<<<NE / 8, 256>>>(coord);

    // ef = tf32(SiLU(m @ We2^T + be2))
    egemm<EMODE_EF><<<NE / 128, 256, ESMEMB>>>(pm, pWe2t, be2, pef, nullptr, nullptr);

    // phi = SiLU(ef @ Wc1^T + bc1) . wc2
    egemm<EMODE_PHI><<<NE / 128, 256, ESMEMB>>>(pef, pWc1t, bc1, nullptr, Wc2, pphi);

    // agg (contiguous gather) + coord output
    agg_gather_kernel<<<(NN + 7) / 8, 256>>>();
    coord_out_kernel<<<(NN + 7) / 8, 256>>>(coord, outc);

    // hmid = SiLU([h | agg] @ Wn1^T + bn1)
    gemm_kernel<MODE_CAT><<<dim3((NN + BM - 1) / BM, 1), 256, SMEMB>>>(
        h, pagg, Wn1, bn1, phmid, 256, NN, 512, nullptr);

    // h_out = hmid @ Wn2^T + bn2 + h
    gemm_kernel<MODE_NODE2><<<dim3((NN + BM - 1) / BM, 1), 256, SMEMB>>>(
        phmid, nullptr, Wn2, bn2, outh, 256, NN, 256, h);
}